// round 1
// baseline (speedup 1.0000x reference)
#include <cuda_runtime.h>

#define NNODES 64
#define NEDGES 128
#define NGRAPH 4

// ---------------- scratch (no allocations allowed) ----------------
__device__ float g_Y [NNODES * 12000];   // max 6*O = 12000 (layer 1)
__device__ float g_h1[NNODES * 2000];
__device__ float g_h2[NNODES * 500];
__device__ float g_h3[NNODES * 100];
__device__ float g_t1[NGRAPH * 1000];
__device__ float g_t2[NGRAPH * 100];

// ---------------- zero scratch (for split-K atomic accumulation) ----------------
__global__ void zero_k(float* __restrict__ p, int n) {
    int i = blockIdx.x * blockDim.x + threadIdx.x;
    if (i < n) p[i] = 0.f;
}

// ---------------- fused "concatenated-B" GEMM ----------------
// Y[n, c] = sum_k A[n,k] * B(k,c),  c in [0, 6*O)
//   blk = c / O, o = c % O
//   blk<4 : We[blk*K*O + k*O + o]   (edge-MLP weight, per a)
//   blk=4 : be[k*O + o]             (edge-MLP bias   -> per-node "yb")
//   blk=5 : root[k*O + o]           (root weight)
// BM=64 (all rows), BN=32, BK=32, 128 threads, 4x4 thread tile.
__global__ __launch_bounds__(128) void gemm_cat(
    const float* __restrict__ A, int K, int O,
    const float* __restrict__ We, const float* __restrict__ be,
    const float* __restrict__ root, float* __restrict__ Y, int kChunk)
{
    __shared__ float As[NNODES][33];   // [m][kk], padded
    __shared__ float Bs[32][32];       // [kk][cl]

    const int t  = threadIdx.x;
    const int c0 = blockIdx.x * 32;
    const int NC = 6 * O;
    const int k0   = blockIdx.y * kChunk;
    const int kend = min(k0 + kChunk, K);

    const int tx = t & 7;    // col group: cols 4*tx .. 4*tx+3
    const int ty = t >> 3;   // row base : rows ty, ty+16, ty+32, ty+48

    float acc[4][4] = {};

    for (int kt = k0; kt < kend; kt += 32) {
        const int kb = min(32, kend - kt);
        // load A tile (64 x 32)
        for (int i = t; i < NNODES * 32; i += 128) {
            int m = i >> 5, kk = i & 31;
            As[m][kk] = (kk < kb) ? A[m * K + kt + kk] : 0.f;
        }
        // load B tile (32 x 32) from the concatenated layout
        for (int i = t; i < 32 * 32; i += 128) {
            int kk = i >> 5, cl = i & 31;
            int cg = c0 + cl;
            float v = 0.f;
            if (cg < NC && kk < kb) {
                int blk = cg / O;
                int o   = cg - blk * O;
                const float* P = (blk < 4) ? (We + (size_t)blk * K * O)
                                           : ((blk == 4) ? be : root);
                v = P[(size_t)(kt + kk) * O + o];
            }
            Bs[kk][cl] = v;
        }
        __syncthreads();

        #pragma unroll 4
        for (int kk = 0; kk < 32; kk++) {
            float4 bv = *reinterpret_cast<const float4*>(&Bs[kk][4 * tx]);
            #pragma unroll
            for (int r = 0; r < 4; r++) {
                float a = As[ty + 16 * r][kk];
                acc[r][0] += a * bv.x;
                acc[r][1] += a * bv.y;
                acc[r][2] += a * bv.z;
                acc[r][3] += a * bv.w;
            }
        }
        __syncthreads();
    }

    const bool single = (gridDim.y == 1);
    #pragma unroll
    for (int r = 0; r < 4; r++) {
        int m = ty + 16 * r;
        #pragma unroll
        for (int j = 0; j < 4; j++) {
            int c = c0 + 4 * tx + j;
            if (c < NC) {
                if (single) Y[(size_t)m * NC + c] = acc[r][j];
                else        atomicAdd(&Y[(size_t)m * NC + c], acc[r][j]);
            }
        }
    }
}

// ---------------- edge combine: message + scatter-add + root + bias + relu ----
// h[n,o] = relu( sum_{e: dst=n} ( sum_a ea[e,a]*Y[src,a*O+o] + Y[src,4O+o] )
//               + Y[n, 5O+o] + b[o] )
// One block per 128-column tile; thread owns one column -> race-free smem accum.
__global__ __launch_bounds__(128) void combine_agg(
    const float* __restrict__ Y, int O,
    const int* __restrict__ eidx, const float* __restrict__ eattr,
    const float* __restrict__ bias, float* __restrict__ h)
{
    __shared__ float agg[NNODES * 128];          // 32 KB
    __shared__ int   sS[NEDGES], sD[NEDGES];
    __shared__ float sEA[NEDGES][4];

    const int t = threadIdx.x;
    const int c = blockIdx.x * 128 + t;
    const int NC = 6 * O;

    for (int i = t; i < NEDGES; i += 128) {
        sS[i] = eidx[i];
        sD[i] = eidx[NEDGES + i];
        sEA[i][0] = eattr[i * 4 + 0];
        sEA[i][1] = eattr[i * 4 + 1];
        sEA[i][2] = eattr[i * 4 + 2];
        sEA[i][3] = eattr[i * 4 + 3];
    }
    for (int n = 0; n < NNODES; n++) agg[n * 128 + t] = 0.f;
    __syncthreads();

    const bool act = (c < O);
    #pragma unroll 4
    for (int e = 0; e < NEDGES; e++) {
        int s = sS[e], d = sD[e];
        if (act) {
            const float* ys = Y + (size_t)s * NC;
            float v = sEA[e][0] * ys[c]
                    + sEA[e][1] * ys[O + c]
                    + sEA[e][2] * ys[2 * O + c]
                    + sEA[e][3] * ys[3 * O + c]
                    + ys[4 * O + c];                 // be-block ("yb")
            agg[d * 128 + t] += v;
        }
    }
    if (act) {
        float bb = bias[c];
        for (int n = 0; n < NNODES; n++) {
            float v = agg[n * 128 + t] + Y[(size_t)n * NC + 5 * O + c] + bb;
            h[n * O + c] = fmaxf(v, 0.f);
        }
    }
}

// ---------------- head: graph readout + FC1 (relu) ----------------
__global__ __launch_bounds__(128) void head1(
    const float* __restrict__ h3, const int* __restrict__ batch,
    const float* __restrict__ W1, const float* __restrict__ c1,
    float* __restrict__ t1)
{
    __shared__ float gS[NGRAPH * 100];
    const int t = threadIdx.x;
    for (int i = t; i < NGRAPH * 100; i += 128) gS[i] = 0.f;
    __syncthreads();
    for (int n = 0; n < NNODES; n++) {       // sequential, race-free per column
        int bg = batch[n];
        if (t < 100) gS[bg * 100 + t] += h3[n * 100 + t];
    }
    __syncthreads();
    int f = blockIdx.x * 128 + t;
    if (f < 1000) {
        float a0 = c1[f], a1 = c1[f], a2 = c1[f], a3 = c1[f];
        for (int k = 0; k < 100; k++) {
            float w = W1[k * 1000 + f];
            a0 += gS[k]       * w;
            a1 += gS[100 + k] * w;
            a2 += gS[200 + k] * w;
            a3 += gS[300 + k] * w;
        }
        t1[f]        = fmaxf(a0, 0.f);
        t1[1000 + f] = fmaxf(a1, 0.f);
        t1[2000 + f] = fmaxf(a2, 0.f);
        t1[3000 + f] = fmaxf(a3, 0.f);
    }
}

// ---------------- head: FC2 (relu), K=1000 ----------------
__global__ __launch_bounds__(256) void head2(
    const float* __restrict__ t1, const float* __restrict__ W2,
    const float* __restrict__ c2, float* __restrict__ t2)
{
    int idx = blockIdx.x * 256 + threadIdx.x;
    int gi = idx / 100, f = idx % 100;
    if (gi < NGRAPH) {
        float acc = c2[f];
        const float* row = t1 + gi * 1000;
        for (int k = 0; k < 1000; k++)
            acc += row[k] * W2[k * 100 + f];
        t2[gi * 100 + f] = fmaxf(acc, 0.f);
    }
}

// ---------------- head: FC3 (relu) + final linear ----------------
__global__ __launch_bounds__(256) void head3(
    const float* __restrict__ t2, const float* __restrict__ W3,
    const float* __restrict__ c3, const float* __restrict__ W4,
    const float* __restrict__ c4, float* __restrict__ out)
{
    __shared__ float g3[NGRAPH * 50];
    const int t = threadIdx.x;
    if (t < 200) {
        int gi = t / 50, f = t % 50;
        float acc = c3[f];
        const float* row = t2 + gi * 100;
        for (int k = 0; k < 100; k++)
            acc += row[k] * W3[k * 50 + f];
        g3[gi * 50 + f] = fmaxf(acc, 0.f);
    }
    __syncthreads();
    if (t < NGRAPH) {
        float acc = c4[0];
        for (int k = 0; k < 50; k++)
            acc += g3[t * 50 + k] * W4[k];
        out[t] = acc;
    }
}

// ---------------- launch ----------------
extern "C" void kernel_launch(void* const* d_in, const int* in_sizes, int n_in,
                              void* d_out, int out_size)
{
    const float* x     = (const float*)d_in[0];
    const int*   eidx  = (const int*)  d_in[1];
    const float* eattr = (const float*)d_in[2];
    const int*   batch = (const int*)  d_in[3];
    const float *We1 = (const float*)d_in[4],  *be1 = (const float*)d_in[5];
    const float *ro1 = (const float*)d_in[6],  *b1  = (const float*)d_in[7];
    const float *We2 = (const float*)d_in[8],  *be2 = (const float*)d_in[9];
    const float *ro2 = (const float*)d_in[10], *b2  = (const float*)d_in[11];
    const float *We3 = (const float*)d_in[12], *be3 = (const float*)d_in[13];
    const float *ro3 = (const float*)d_in[14], *b3  = (const float*)d_in[15];
    const float *W1  = (const float*)d_in[16], *c1  = (const float*)d_in[17];
    const float *W2  = (const float*)d_in[18], *c2  = (const float*)d_in[19];
    const float *W3  = (const float*)d_in[20], *c3  = (const float*)d_in[21];
    const float *W4  = (const float*)d_in[22], *c4  = (const float*)d_in[23];

    float *Y, *h1, *h2, *h3, *t1, *t2;
    cudaGetSymbolAddress((void**)&Y,  g_Y);
    cudaGetSymbolAddress((void**)&h1, g_h1);
    cudaGetSymbolAddress((void**)&h2, g_h2);
    cudaGetSymbolAddress((void**)&h3, g_h3);
    cudaGetSymbolAddress((void**)&t1, g_t1);
    cudaGetSymbolAddress((void**)&t2, g_t2);

    // Layer 1: K=9, O=2000  (Ncols = 12000 -> 375 col-blocks, no split-K)
    gemm_cat<<<dim3(375, 1), 128>>>(x, 9, 2000, We1, be1, ro1, Y, 9);
    combine_agg<<<16, 128>>>(Y, 2000, eidx, eattr, b1, h1);

    // Layer 2: K=2000, O=500 (Ncols = 3000 -> 94 col-blocks, split-K = 4)
    zero_k<<<(NNODES * 3000 + 255) / 256, 256>>>(Y, NNODES * 3000);
    gemm_cat<<<dim3(94, 4), 128>>>(h1, 2000, 500, We2, be2, ro2, Y, 500);
    combine_agg<<<4, 128>>>(Y, 500, eidx, eattr, b2, h2);

    // Layer 3: K=500, O=100 (Ncols = 600 -> 19 col-blocks, split-K = 6)
    zero_k<<<(NNODES * 600 + 255) / 256, 256>>>(Y, NNODES * 600);
    gemm_cat<<<dim3(19, 6), 128>>>(h2, 500, 100, We3, be3, ro3, Y, 84);
    combine_agg<<<1, 128>>>(Y, 100, eidx, eattr, b3, h3);

    // Head
    head1<<<8, 128>>>(h3, batch, W1, c1, t1);
    head2<<<2, 256>>>(t1, W2, c2, t2);
    head3<<<1, 256>>>(t2, W3, c3, W4, c4, (float*)d_out);
}

// round 3
// speedup vs baseline: 1.6402x; 1.6402x over previous
#include <cuda_runtime.h>
#include <cstdint>

#define NNODES 64
#define NEDGES 128
#define NGRAPH 4

// ---------------- scratch (no allocations allowed) ----------------
__device__ float g_Y  [NNODES * 12000];          // cat-GEMM output (max layer 1)
__device__ float g_Yp [16 * NNODES * 3000];      // split-K partials (max: L2, 16 slices)
__device__ float g_xT [16 * NNODES];             // x transposed [K][64]
__device__ float g_h1 [NNODES * 2000];
__device__ float g_h1T[2000 * NNODES];
__device__ float g_h2 [NNODES * 500];
__device__ float g_h2T[500 * NNODES];
__device__ float g_h3 [NNODES * 100];
__device__ float g_h3T[100 * NNODES];
__device__ float g_t1 [NGRAPH * 1000];
__device__ float g_t2 [NGRAPH * 100];

__global__ void zero_k(float* __restrict__ p, int n) {
    int i = blockIdx.x * blockDim.x + threadIdx.x;
    if (i < n) p[i] = 0.f;
}

// x [64,9] -> xT [9,64]
__global__ void transpose_x(const float* __restrict__ x, float* __restrict__ xT) {
    int t = threadIdx.x;
    if (t < NNODES)
        for (int a = 0; a < 9; a++) xT[a * NNODES + t] = x[t * 9 + a];
}

// ---------------- cp.async helpers ----------------
__device__ __forceinline__ void cpa16_cg(void* dst, const void* src) {
    uint32_t d = (uint32_t)__cvta_generic_to_shared(dst);
    asm volatile("cp.async.cg.shared.global [%0], [%1], 16;\n" :: "r"(d), "l"(src));
}
__device__ __forceinline__ void cpa16_ca(void* dst, const void* src) {
    uint32_t d = (uint32_t)__cvta_generic_to_shared(dst);
    asm volatile("cp.async.ca.shared.global [%0], [%1], 16;\n" :: "r"(d), "l"(src));
}

// ---------------- fused "concatenated-B" GEMM ----------------
// Y[m, c] = sum_k AT[k, m] * B(k, c),  c in [0, 6*O):
//   blk = c/O :  blk<4 -> We[blk*K*O + k*O + o], blk=4 -> be[k*O+o], blk=5 -> root[k*O+o]
// BM=64 (all rows), BN=64, BK=16, 128 threads, 8x4 thread tile,
// double-buffered cp.async pipeline, split-K slices written to Yp[by].
__global__ __launch_bounds__(128) void gemm_cat(
    const float* __restrict__ AT, int K, int O,
    const float* __restrict__ We, const float* __restrict__ be,
    const float* __restrict__ root, float* __restrict__ Yp, int kChunk)
{
    __shared__ float As[2][16][68];   // [buf][kk][m], padded (272B rows, 16B-aligned)
    __shared__ float Bs[2][16][64];   // [buf][kk][cl]

    const int t   = threadIdx.x;
    const int NC  = 6 * O;
    const int c0  = blockIdx.x * 64;
    const int k0  = blockIdx.y * kChunk;
    const int kend = min(k0 + kChunk, K);
    const int nsteps = (kend - k0 + 15) >> 4;

    // fixed per-thread load assignment: column/m group g (4 wide), kk = kkb and kkb+8
    const int g   = t & 15;
    const int kkb = t >> 4;

    const int cg = c0 + 4 * g;
    const float* Bbase = nullptr;
    const bool bvalid = (cg < NC);
    if (bvalid) {
        int blk = cg / O;
        int o   = cg - blk * O;
        const float* P = (blk < 4) ? (We + (size_t)blk * K * O)
                                   : ((blk == 4) ? be : root);
        Bbase = P + o;
    }
    const float4 z4 = make_float4(0.f, 0.f, 0.f, 0.f);

    // stage s into buffer buf
    auto stage = [&](int s, int buf) {
        int kt = k0 + s * 16;
        int kb = min(16, kend - kt);
        #pragma unroll
        for (int i = 0; i < 2; i++) {
            int kk = kkb + 8 * i;
            float4* bd = (float4*)&Bs[buf][kk][4 * g];
            if (bvalid && kk < kb) cpa16_cg(bd, Bbase + (size_t)(kt + kk) * O);
            else                   *bd = z4;
            float4* ad = (float4*)&As[buf][kk][4 * g];
            if (kk < kb) cpa16_ca(ad, AT + (size_t)(kt + kk) * NNODES + 4 * g);
            else         *ad = z4;
        }
        asm volatile("cp.async.commit_group;\n" ::: "memory");
    };

    stage(0, 0);

    const int tx = t & 15;   // cols 4*tx..+3
    const int ty = t >> 4;   // rows ty*4..+3 and 32+ty*4..+3
    float acc[8][4] = {};

    for (int s = 0; s < nsteps; s++) {
        const int cur = s & 1;
        if (s + 1 < nsteps) {
            stage(s + 1, cur ^ 1);
            asm volatile("cp.async.wait_group 1;\n" ::: "memory");
        } else {
            asm volatile("cp.async.wait_group 0;\n" ::: "memory");
        }
        __syncthreads();

        #pragma unroll
        for (int kk = 0; kk < 16; kk++) {
            float4 a0 = *(const float4*)&As[cur][kk][ty * 4];
            float4 a1 = *(const float4*)&As[cur][kk][32 + ty * 4];
            float4 b  = *(const float4*)&Bs[cur][kk][tx * 4];
            acc[0][0] += a0.x * b.x; acc[0][1] += a0.x * b.y; acc[0][2] += a0.x * b.z; acc[0][3] += a0.x * b.w;
            acc[1][0] += a0.y * b.x; acc[1][1] += a0.y * b.y; acc[1][2] += a0.y * b.z; acc[1][3] += a0.y * b.w;
            acc[2][0] += a0.z * b.x; acc[2][1] += a0.z * b.y; acc[2][2] += a0.z * b.z; acc[2][3] += a0.z * b.w;
            acc[3][0] += a0.w * b.x; acc[3][1] += a0.w * b.y; acc[3][2] += a0.w * b.z; acc[3][3] += a0.w * b.w;
            acc[4][0] += a1.x * b.x; acc[4][1] += a1.x * b.y; acc[4][2] += a1.x * b.z; acc[4][3] += a1.x * b.w;
            acc[5][0] += a1.y * b.x; acc[5][1] += a1.y * b.y; acc[5][2] += a1.y * b.z; acc[5][3] += a1.y * b.w;
            acc[6][0] += a1.z * b.x; acc[6][1] += a1.z * b.y; acc[6][2] += a1.z * b.z; acc[6][3] += a1.z * b.w;
            acc[7][0] += a1.w * b.x; acc[7][1] += a1.w * b.y; acc[7][2] += a1.w * b.z; acc[7][3] += a1.w * b.w;
        }
        __syncthreads();
    }

    // epilogue: plain stores into this slice's partial buffer
    const int c = c0 + 4 * tx;
    if (c < NC) {
        float* Yo = Yp + (size_t)blockIdx.y * (NNODES * (size_t)NC);
        #pragma unroll
        for (int r = 0; r < 8; r++) {
            int m = (r < 4) ? (ty * 4 + r) : (32 + ty * 4 + (r - 4));
            *(float4*)&Yo[(size_t)m * NC + c] =
                make_float4(acc[r][0], acc[r][1], acc[r][2], acc[r][3]);
        }
    }
}

// ---------------- split-K reduction: Y[i] = sum_s Yp[s*len + i] ----------------
__global__ void reduce_k(const float* __restrict__ Yp, float* __restrict__ Y,
                         int len, int S)
{
    int i = blockIdx.x * 256 + threadIdx.x;
    if (i < len) {
        float s = 0.f;
        for (int j = 0; j < S; j++) s += Yp[(size_t)j * len + i];
        Y[i] = s;
    }
}

// ---------------- edge combine: message + scatter-add + root + bias + relu ----
// Also emits the transposed activation hT[c*64+n] for the next GEMM's A loads.
__global__ __launch_bounds__(128) void combine_agg(
    const float* __restrict__ Y, int O,
    const int* __restrict__ eidx, const float* __restrict__ eattr,
    const float* __restrict__ bias, float* __restrict__ h, float* __restrict__ hT)
{
    __shared__ float agg[NNODES * 128];
    __shared__ int   sS[NEDGES], sD[NEDGES];
    __shared__ float sEA[NEDGES][4];

    const int t = threadIdx.x;
    const int c = blockIdx.x * 128 + t;
    const int NC = 6 * O;

    for (int i = t; i < NEDGES; i += 128) {
        sS[i] = eidx[i];
        sD[i] = eidx[NEDGES + i];
        sEA[i][0] = eattr[i * 4 + 0];
        sEA[i][1] = eattr[i * 4 + 1];
        sEA[i][2] = eattr[i * 4 + 2];
        sEA[i][3] = eattr[i * 4 + 3];
    }
    for (int n = 0; n < NNODES; n++) agg[n * 128 + t] = 0.f;
    __syncthreads();

    const bool act = (c < O);
    #pragma unroll 4
    for (int e = 0; e < NEDGES; e++) {
        int s = sS[e], d = sD[e];
        if (act) {
            const float* ys = Y + (size_t)s * NC;
            float v = sEA[e][0] * ys[c]
                    + sEA[e][1] * ys[O + c]
                    + sEA[e][2] * ys[2 * O + c]
                    + sEA[e][3] * ys[3 * O + c]
                    + ys[4 * O + c];
            agg[d * 128 + t] += v;
        }
    }
    if (act) {
        float bb = bias[c];
        for (int n = 0; n < NNODES; n++) {
            float v = agg[n * 128 + t] + Y[(size_t)n * NC + 5 * O + c] + bb;
            v = fmaxf(v, 0.f);
            h [n * O + c]          = v;
            hT[(size_t)c * NNODES + n] = v;
        }
    }
}

// ---------------- head: graph readout + FC1 (relu) ----------------
__global__ __launch_bounds__(128) void head1(
    const float* __restrict__ h3, const int* __restrict__ batch,
    const float* __restrict__ W1, const float* __restrict__ c1,
    float* __restrict__ t1)
{
    __shared__ float gS[NGRAPH * 100];
    const int t = threadIdx.x;
    for (int i = t; i < NGRAPH * 100; i += 128) gS[i] = 0.f;
    __syncthreads();
    for (int n = 0; n < NNODES; n++) {
        int bg = batch[n];
        if (t < 100) gS[bg * 100 + t] += h3[n * 100 + t];
    }
    __syncthreads();
    int f = blockIdx.x * 128 + t;
    if (f < 1000) {
        float a0 = c1[f], a1 = c1[f], a2 = c1[f], a3 = c1[f];
        for (int k = 0; k < 100; k++) {
            float w = W1[k * 1000 + f];
            a0 += gS[k]       * w;
            a1 += gS[100 + k] * w;
            a2 += gS[200 + k] * w;
            a3 += gS[300 + k] * w;
        }
        t1[f]        = fmaxf(a0, 0.f);
        t1[1000 + f] = fmaxf(a1, 0.f);
        t1[2000 + f] = fmaxf(a2, 0.f);
        t1[3000 + f] = fmaxf(a3, 0.f);
    }
}

// ---------------- head: FC2 split over k (pre-activation, atomic) ----------------
// grid (4 graphs, 4 k-slices); t2 must be zeroed first; relu applied by head3.
__global__ __launch_bounds__(128) void head2(
    const float* __restrict__ t1, const float* __restrict__ W2,
    const float* __restrict__ c2, float* __restrict__ t2)
{
    const int f  = threadIdx.x;
    const int gi = blockIdx.x;
    const int k0 = blockIdx.y * 250;
    if (f < 100) {
        float acc = (blockIdx.y == 0) ? c2[f] : 0.f;
        const float* row = t1 + gi * 1000;
        #pragma unroll 5
        for (int k = k0; k < k0 + 250; k++)
            acc += row[k] * W2[k * 100 + f];
        atomicAdd(&t2[gi * 100 + f], acc);
    }
}

// ---------------- head: FC3 (relu-on-read) + final linear ----------------
__global__ __launch_bounds__(256) void head3(
    const float* __restrict__ t2, const float* __restrict__ W3,
    const float* __restrict__ c3, const float* __restrict__ W4,
    const float* __restrict__ c4, float* __restrict__ out)
{
    __shared__ float g3[NGRAPH * 50];
    const int t = threadIdx.x;
    if (t < 200) {
        int gi = t / 50, f = t % 50;
        float acc = c3[f];
        const float* row = t2 + gi * 100;
        for (int k = 0; k < 100; k++)
            acc += fmaxf(row[k], 0.f) * W3[k * 50 + f];
        g3[gi * 50 + f] = fmaxf(acc, 0.f);
    }
    __syncthreads();
    if (t < NGRAPH) {
        float acc = c4[0];
        for (int k = 0; k < 50; k++)
            acc += g3[t * 50 + k] * W4[k];
        out[t] = acc;
    }
}

// ---------------- launch ----------------
extern "C" void kernel_launch(void* const* d_in, const int* in_sizes, int n_in,
                              void* d_out, int out_size)
{
    const float* x     = (const float*)d_in[0];
    const int*   eidx  = (const int*)  d_in[1];
    const float* eattr = (const float*)d_in[2];
    const int*   batch = (const int*)  d_in[3];
    const float *We1 = (const float*)d_in[4],  *be1 = (const float*)d_in[5];
    const float *ro1 = (const float*)d_in[6],  *b1  = (const float*)d_in[7];
    const float *We2 = (const float*)d_in[8],  *be2 = (const float*)d_in[9];
    const float *ro2 = (const float*)d_in[10], *b2  = (const float*)d_in[11];
    const float *We3 = (const float*)d_in[12], *be3 = (const float*)d_in[13];
    const float *ro3 = (const float*)d_in[14], *b3  = (const float*)d_in[15];
    const float *W1  = (const float*)d_in[16], *c1  = (const float*)d_in[17];
    const float *W2  = (const float*)d_in[18], *c2  = (const float*)d_in[19];
    const float *W3  = (const float*)d_in[20], *c3  = (const float*)d_in[21];
    const float *W4  = (const float*)d_in[22], *c4  = (const float*)d_in[23];

    float *Y, *Yp, *xT, *h1, *h1T, *h2, *h2T, *h3, *h3T, *t1, *t2;
    cudaGetSymbolAddress((void**)&Y,   g_Y);
    cudaGetSymbolAddress((void**)&Yp,  g_Yp);
    cudaGetSymbolAddress((void**)&xT,  g_xT);
    cudaGetSymbolAddress((void**)&h1,  g_h1);
    cudaGetSymbolAddress((void**)&h1T, g_h1T);
    cudaGetSymbolAddress((void**)&h2,  g_h2);
    cudaGetSymbolAddress((void**)&h2T, g_h2T);
    cudaGetSymbolAddress((void**)&h3,  g_h3);
    cudaGetSymbolAddress((void**)&h3T, g_h3T);
    cudaGetSymbolAddress((void**)&t1,  g_t1);
    cudaGetSymbolAddress((void**)&t2,  g_t2);

    transpose_x<<<1, 64>>>(x, xT);

    // Layer 1: K=9, O=2000, NC=12000 -> 188 col tiles, no split-K, direct to Y
    gemm_cat<<<dim3(188, 1), 128>>>(xT, 9, 2000, We1, be1, ro1, Y, 16);
    combine_agg<<<16, 128>>>(Y, 2000, eidx, eattr, b1, h1, h1T);

    // Layer 2: K=2000, O=500, NC=3000 -> 47 col tiles x 16 K-slices
    gemm_cat<<<dim3(47, 16), 128>>>(h1T, 2000, 500, We2, be2, ro2, Yp, 128);
    reduce_k<<<(NNODES * 3000 + 255) / 256, 256>>>(Yp, Y, NNODES * 3000, 16);
    combine_agg<<<4, 128>>>(Y, 500, eidx, eattr, b2, h2, h2T);

    // Layer 3: K=500, O=100, NC=600 -> 10 col tiles x 16 K-slices (kChunk=32)
    gemm_cat<<<dim3(10, 16), 128>>>(h2T, 500, 100, We3, be3, ro3, Yp, 32);
    reduce_k<<<(NNODES * 600 + 255) / 256, 256>>>(Yp, Y, NNODES * 600, 16);
    combine_agg<<<1, 128>>>(Y, 100, eidx, eattr, b3, h3, h3T);

    // Head
    head1<<<8, 128>>>(h3, batch, W1, c1, t1);
    zero_k<<<2, 256>>>(t2, NGRAPH * 100);
    head2<<<dim3(NGRAPH, 4), 128>>>(t1, W2, c2, t2);
    head3<<<1, 256>>>(t2, W3, c3, W4, c4, (float*)d_out);
}

// round 4
// speedup vs baseline: 3.2307x; 1.9697x over previous
#include <cuda_runtime.h>
#include <cstdint>

#define NNODES 64
#define NEDGES 128
#define NGRAPH 4

typedef unsigned long long ull;

// ---------------- scratch ----------------
__device__ float g_Y  [NNODES * 12000];
__device__ float g_Yp [16 * NNODES * 3000];
__device__ float g_xT [16 * NNODES];
__device__ float g_Pt [384 * NNODES];      // P transposed: [r][n]
__device__ float g_h1T[2000 * NNODES];
__device__ float g_h2T[500 * NNODES];
__device__ float g_h3 [NNODES * 100];

// ---------------- f32x2 helpers ----------------
__device__ __forceinline__ ull dup2(float x) {
    ull r; asm("mov.b64 %0, {%1, %1};" : "=l"(r) : "f"(x)); return r;
}
__device__ __forceinline__ void fma2(ull &d, ull a, ull b) {
    asm("fma.rn.f32x2 %0, %1, %2, %3;" : "=l"(d) : "l"(a), "l"(b), "l"(d));
}
__device__ __forceinline__ float2 unpk(ull v) {
    float2 r; asm("mov.b64 {%0, %1}, %2;" : "=f"(r.x), "=f"(r.y) : "l"(v)); return r;
}

// ---------------- cp.async helpers ----------------
__device__ __forceinline__ void cpa16(void* dst, const void* src) {
    uint32_t d = (uint32_t)__cvta_generic_to_shared(dst);
    asm volatile("cp.async.cg.shared.global [%0], [%1], 16;\n" :: "r"(d), "l"(src));
}
__device__ __forceinline__ void cpa_commit() {
    asm volatile("cp.async.commit_group;\n" ::: "memory");
}
__device__ __forceinline__ void cpa_wait1() {
    asm volatile("cp.async.wait_group 1;\n" ::: "memory");
}
__device__ __forceinline__ void cpa_wait0() {
    asm volatile("cp.async.wait_group 0;\n" ::: "memory");
}

// ---------------- prep: xT + edge-structure matrix P ----------------
__global__ void prep(const float* __restrict__ x,
                     const int* __restrict__ eidx,
                     const float* __restrict__ eattr,
                     float* __restrict__ xT, float* __restrict__ Pt)
{
    const int t = threadIdx.x;  // 128
    for (int i = t; i < 384 * NNODES; i += 128) Pt[i] = 0.f;
    if (t < NNODES)
        for (int a = 0; a < 9; a++) xT[a * NNODES + t] = x[t * 9 + a];
    __syncthreads();
    if (t < NEDGES) {
        int s = eidx[t], d = eidx[NEDGES + t];
        #pragma unroll
        for (int j = 0; j < 4; j++)
            atomicAdd(&Pt[(s * 5 + j) * NNODES + d], eattr[t * 4 + j]);
        atomicAdd(&Pt[(s * 5 + 4) * NNODES + d], 1.f);
    }
    __syncthreads();
    if (t < NNODES) Pt[(320 + t) * NNODES + t] = 1.f;   // root-block identity
}

// ---------------- fused "concatenated-B" GEMM (f32x2 inner) ----------------
// Y[m, c] = sum_k AT[k, m] * Bcat(k, c),  c in [0, 6*O)
__global__ __launch_bounds__(128) void gemm_cat(
    const float* __restrict__ AT, int K, int O,
    const float* __restrict__ We, const float* __restrict__ be,
    const float* __restrict__ root, float* __restrict__ Yp, int kChunk)
{
    __shared__ float As[2][16][68];
    __shared__ float Bs[2][16][64];

    const int t   = threadIdx.x;
    const int NC  = 6 * O;
    const int c0  = blockIdx.x * 64;
    const int k0  = blockIdx.y * kChunk;
    const int kend = min(k0 + kChunk, K);
    const int nsteps = (kend - k0 + 15) >> 4;

    const int g   = t & 15;
    const int kkb = t >> 4;

    const int cg = c0 + 4 * g;
    const float* Bbase = nullptr;
    const bool bvalid = (cg < NC);
    if (bvalid) {
        int blk = cg / O;
        int o   = cg - blk * O;
        const float* P = (blk < 4) ? (We + (size_t)blk * K * O)
                                   : ((blk == 4) ? be : root);
        Bbase = P + o;
    }
    const float4 z4 = make_float4(0.f, 0.f, 0.f, 0.f);

    auto stage = [&](int s, int buf) {
        int kt = k0 + s * 16;
        int kb = min(16, kend - kt);
        #pragma unroll
        for (int i = 0; i < 2; i++) {
            int kk = kkb + 8 * i;
            float4* bd = (float4*)&Bs[buf][kk][4 * g];
            if (bvalid && kk < kb) cpa16(bd, Bbase + (size_t)(kt + kk) * O);
            else                   *bd = z4;
            float4* ad = (float4*)&As[buf][kk][4 * g];
            if (kk < kb) cpa16(ad, AT + (size_t)(kt + kk) * NNODES + 4 * g);
            else         *ad = z4;
        }
        cpa_commit();
    };

    stage(0, 0);

    const int tx = t & 15;   // cols 4*tx..+3
    const int ty = t >> 4;   // rows 4*ty..+3 and 32+4*ty..+3
    ull acc[4][4];           // [rowpair][col]
    #pragma unroll
    for (int r = 0; r < 4; r++)
        #pragma unroll
        for (int j = 0; j < 4; j++) acc[r][j] = 0ull;

    for (int s = 0; s < nsteps; s++) {
        const int cur = s & 1;
        if (s + 1 < nsteps) { stage(s + 1, cur ^ 1); cpa_wait1(); }
        else                { cpa_wait0(); }
        __syncthreads();

        #pragma unroll
        for (int kk = 0; kk < 16; kk++) {
            const float* as = &As[cur][kk][0];
            ull a0 = *(const ull*)(as + 4 * ty);
            ull a1 = *(const ull*)(as + 4 * ty + 2);
            ull a2 = *(const ull*)(as + 32 + 4 * ty);
            ull a3 = *(const ull*)(as + 32 + 4 * ty + 2);
            float4 b = *(const float4*)&Bs[cur][kk][4 * tx];
            ull b0 = dup2(b.x), b1 = dup2(b.y), b2 = dup2(b.z), b3 = dup2(b.w);
            fma2(acc[0][0], a0, b0); fma2(acc[0][1], a0, b1);
            fma2(acc[0][2], a0, b2); fma2(acc[0][3], a0, b3);
            fma2(acc[1][0], a1, b0); fma2(acc[1][1], a1, b1);
            fma2(acc[1][2], a1, b2); fma2(acc[1][3], a1, b3);
            fma2(acc[2][0], a2, b0); fma2(acc[2][1], a2, b1);
            fma2(acc[2][2], a2, b2); fma2(acc[2][3], a2, b3);
            fma2(acc[3][0], a3, b0); fma2(acc[3][1], a3, b1);
            fma2(acc[3][2], a3, b2); fma2(acc[3][3], a3, b3);
        }
        __syncthreads();
    }

    const int c = c0 + 4 * tx;
    if (c < NC) {
        float* Yo = Yp + (size_t)blockIdx.y * (NNODES * (size_t)NC);
        #pragma unroll
        for (int r = 0; r < 4; r++) {
            int m = (r < 2) ? (4 * ty + 2 * r) : (32 + 4 * ty + 2 * (r - 2));
            float2 v0 = unpk(acc[r][0]), v1 = unpk(acc[r][1]);
            float2 v2 = unpk(acc[r][2]), v3 = unpk(acc[r][3]);
            *(float4*)&Yo[(size_t)m * NC + c]       = make_float4(v0.x, v1.x, v2.x, v3.x);
            *(float4*)&Yo[(size_t)(m + 1) * NC + c] = make_float4(v0.y, v1.y, v2.y, v3.y);
        }
    }
}

// ---------------- split-K reduction ----------------
__global__ void reduce_k(const float* __restrict__ Yp, float* __restrict__ Y,
                         int len, int S)
{
    int i = blockIdx.x * 256 + threadIdx.x;
    if (i < len) {
        float s = 0.f;
        for (int j = 0; j < S; j++) s += Yp[(size_t)j * len + i];
        Y[i] = s;
    }
}

// ---------------- combine as GEMM: h = relu(P^T-mix of Y + b) ----------------
// h[m, c] = relu( sum_{r<384} Pt[r][m] * Yg[r, c] + b[c] ),
// Yg[r, c]: r<320 -> Y[r/5, (r%5)*O + c];  r>=320 -> Y[r-320, 5*O + c]
// BM=64, BN=32, BK=16, K=384 (24 steps), 128 threads, 4x4 tile (f32x2).
__global__ __launch_bounds__(128) void combine_gemm(
    const float* __restrict__ Y, int O, const float* __restrict__ Pt,
    const float* __restrict__ bias, float* __restrict__ h, float* __restrict__ hT)
{
    __shared__ float As[2][16][68];
    __shared__ float Bs[2][16][32];

    const int t  = threadIdx.x;
    const int NC = 6 * O;
    const int c0 = blockIdx.x * 32;

    // B load assignment: one float4 per thread
    const int kkB = t >> 3;
    const int clB = (t & 7) * 4;
    const bool bvalid = (c0 + clB < O);
    // A load assignment: two float4 per thread
    const float4 z4 = make_float4(0.f, 0.f, 0.f, 0.f);

    auto stage = [&](int s, int buf) {
        int kt = s * 16;
        {
            int r = kt + kkB;
            int sN, jb;
            if (r < 320) { sN = r / 5; jb = r - 5 * sN; }
            else         { sN = r - 320; jb = 5; }
            float4* bd = (float4*)&Bs[buf][kkB][clB];
            if (bvalid) cpa16(bd, Y + (size_t)sN * NC + (size_t)jb * O + c0 + clB);
            else        *bd = z4;
        }
        #pragma unroll
        for (int i = 0; i < 2; i++) {
            int q  = t + 128 * i;
            int kk = q >> 4;
            int m4 = (q & 15) * 4;
            cpa16(&As[buf][kk][m4], Pt + (size_t)(kt + kk) * NNODES + m4);
        }
        cpa_commit();
    };

    stage(0, 0);

    const int tx = t & 7;    // cols 4*tx..+3
    const int ty = t >> 3;   // rows 4*ty..+3
    ull acc[2][4];
    #pragma unroll
    for (int r = 0; r < 2; r++)
        #pragma unroll
        for (int j = 0; j < 4; j++) acc[r][j] = 0ull;

    for (int s = 0; s < 24; s++) {
        const int cur = s & 1;
        if (s + 1 < 24) { stage(s + 1, cur ^ 1); cpa_wait1(); }
        else            { cpa_wait0(); }
        __syncthreads();

        #pragma unroll
        for (int kk = 0; kk < 16; kk++) {
            const float* as = &As[cur][kk][0];
            ull a0 = *(const ull*)(as + 4 * ty);
            ull a1 = *(const ull*)(as + 4 * ty + 2);
            float4 b = *(const float4*)&Bs[cur][kk][4 * tx];
            ull b0 = dup2(b.x), b1 = dup2(b.y), b2 = dup2(b.z), b3 = dup2(b.w);
            fma2(acc[0][0], a0, b0); fma2(acc[0][1], a0, b1);
            fma2(acc[0][2], a0, b2); fma2(acc[0][3], a0, b3);
            fma2(acc[1][0], a1, b0); fma2(acc[1][1], a1, b1);
            fma2(acc[1][2], a1, b2); fma2(acc[1][3], a1, b3);
        }
        __syncthreads();
    }

    const int c = c0 + 4 * tx;
    if (c < O) {
        float4 bb = *(const float4*)&bias[c];
        float2 v[2][4];
        #pragma unroll
        for (int r = 0; r < 2; r++)
            #pragma unroll
            for (int j = 0; j < 4; j++) v[r][j] = unpk(acc[r][j]);
        // rows m = 4*ty + {0,1,2,3}
        float row[4][4];
        #pragma unroll
        for (int j = 0; j < 4; j++) {
            float bj = (&bb.x)[j];
            row[0][j] = fmaxf(v[0][j].x + bj, 0.f);
            row[1][j] = fmaxf(v[0][j].y + bj, 0.f);
            row[2][j] = fmaxf(v[1][j].x + bj, 0.f);
            row[3][j] = fmaxf(v[1][j].y + bj, 0.f);
        }
        const int m0 = 4 * ty;
        #pragma unroll
        for (int r = 0; r < 4; r++)
            *(float4*)&h[(size_t)(m0 + r) * O + c] =
                make_float4(row[r][0], row[r][1], row[r][2], row[r][3]);
        #pragma unroll
        for (int j = 0; j < 4; j++)
            *(float4*)&hT[(size_t)(c + j) * NNODES + m0] =
                make_float4(row[0][j], row[1][j], row[2][j], row[3][j]);
    }
}

// ---------------- fused FCN head: one block per graph ----------------
__global__ __launch_bounds__(256) void head_fused(
    const float* __restrict__ h3, const int* __restrict__ batch,
    const float* __restrict__ W1, const float* __restrict__ c1,
    const float* __restrict__ W2, const float* __restrict__ c2,
    const float* __restrict__ W3, const float* __restrict__ c3,
    const float* __restrict__ W4, const float* __restrict__ c4,
    float* __restrict__ out)
{
    __shared__ float gS[100];
    __shared__ float s1[1000];
    __shared__ float part[200];
    __shared__ float s2[100];
    __shared__ float s3[50];
    __shared__ int   sb[NNODES];

    const int g = blockIdx.x;
    const int t = threadIdx.x;

    if (t < NNODES) sb[t] = batch[t];
    __syncthreads();

    if (t < 100) {
        float a = 0.f;
        for (int n = 0; n < NNODES; n++)
            if (sb[n] == g) a += h3[n * 100 + t];
        gS[t] = a;
    }
    __syncthreads();

    // FC1: 1000 outputs, K=100
    for (int f = t; f < 1000; f += 256) {
        float a = c1[f];
        for (int k = 0; k < 100; k++) a += gS[k] * W1[k * 1000 + f];
        s1[f] = fmaxf(a, 0.f);
    }
    __syncthreads();

    // FC2: 100 outputs, K=1000, split k in two halves
    if (t < 200) {
        int f = t % 100, hh = t / 100;
        float a = 0.f;
        int k0 = hh * 500;
        for (int k = k0; k < k0 + 500; k++) a += s1[k] * W2[k * 100 + f];
        part[t] = a;
    }
    __syncthreads();
    if (t < 100) s2[t] = fmaxf(part[t] + part[100 + t] + c2[t], 0.f);
    __syncthreads();

    // FC3: 50 outputs, K=100
    if (t < 50) {
        float a = c3[t];
        for (int k = 0; k < 100; k++) a += s2[k] * W3[k * 50 + t];
        s3[t] = fmaxf(a, 0.f);
    }
    __syncthreads();

    // FC4: 1 output, K=50 (warp 0 reduce)
    if (t < 32) {
        float a = (t < 50) ? s3[t] * W4[t] : 0.f;
        if (t + 32 < 50) a += s3[t + 32] * W4[t + 32];
        #pragma unroll
        for (int o = 16; o > 0; o >>= 1)
            a += __shfl_xor_sync(0xffffffffu, a, o);
        if (t == 0) out[g] = a + c4[0];
    }
}

// ---------------- launch ----------------
extern "C" void kernel_launch(void* const* d_in, const int* in_sizes, int n_in,
                              void* d_out, int out_size)
{
    const float* x     = (const float*)d_in[0];
    const int*   eidx  = (const int*)  d_in[1];
    const float* eattr = (const float*)d_in[2];
    const int*   batch = (const int*)  d_in[3];
    const float *We1 = (const float*)d_in[4],  *be1 = (const float*)d_in[5];
    const float *ro1 = (const float*)d_in[6],  *b1  = (const float*)d_in[7];
    const float *We2 = (const float*)d_in[8],  *be2 = (const float*)d_in[9];
    const float *ro2 = (const float*)d_in[10], *b2  = (const float*)d_in[11];
    const float *We3 = (const float*)d_in[12], *be3 = (const float*)d_in[13];
    const float *ro3 = (const float*)d_in[14], *b3  = (const float*)d_in[15];
    const float *W1  = (const float*)d_in[16], *c1  = (const float*)d_in[17];
    const float *W2  = (const float*)d_in[18], *c2  = (const float*)d_in[19];
    const float *W3  = (const float*)d_in[20], *c3  = (const float*)d_in[21];
    const float *W4  = (const float*)d_in[22], *c4  = (const float*)d_in[23];

    float *Y, *Yp, *xT, *Pt, *h1T, *h2T, *h3;
    cudaGetSymbolAddress((void**)&Y,   g_Y);
    cudaGetSymbolAddress((void**)&Yp,  g_Yp);
    cudaGetSymbolAddress((void**)&xT,  g_xT);
    cudaGetSymbolAddress((void**)&Pt,  g_Pt);
    cudaGetSymbolAddress((void**)&h1T, g_h1T);
    cudaGetSymbolAddress((void**)&h2T, g_h2T);
    cudaGetSymbolAddress((void**)&h3,  g_h3);

    prep<<<1, 128>>>(x, eidx, eattr, xT, Pt);

    // Layer 1: K=9, O=2000, NC=12000 -> 188 tiles, direct to Y (gridDim.y==1 slot 0)
    gemm_cat<<<dim3(188, 1), 128>>>(xT, 9, 2000, We1, be1, ro1, Y, 16);
    // combine writes h1 into Yp area? no: h1 row-major only needed for nothing; hT used by gemm2.
    combine_gemm<<<63, 128>>>(Y, 2000, Pt, b1, Yp /*h1 scratch*/, h1T);

    // Layer 2: K=2000, O=500, NC=3000 -> 47 tiles x 16 K-slices
    gemm_cat<<<dim3(47, 16), 128>>>(h1T, 2000, 500, We2, be2, ro2, Yp, 125);
    reduce_k<<<(NNODES * 3000 + 255) / 256, 256>>>(Yp, Y, NNODES * 3000, 16);
    combine_gemm<<<16, 128>>>(Y, 500, Pt, b2, Yp /*h2 scratch*/, h2T);

    // Layer 3: K=500, O=100, NC=600 -> 10 tiles x 16 K-slices
    gemm_cat<<<dim3(10, 16), 128>>>(h2T, 500, 100, We3, be3, ro3, Yp, 32);
    reduce_k<<<(NNODES * 600 + 255) / 256, 256>>>(Yp, Y, NNODES * 600, 16);
    combine_gemm<<<4, 128>>>(Y, 100, Pt, b3, h3, h2T /*h3T unused but must be writable*/);

    // Head (per-graph blocks)
    head_fused<<<NGRAPH, 256>>>(h3, batch, W1, c1, W2, c2, W3, c3, W4, c4,
                                (float*)d_out);
}